// round 17
// baseline (speedup 1.0000x reference)
#include <cuda_runtime.h>
#include <cuda_fp16.h>
#include <cstdint>
#include <cstddef>

// Problem constants
#define BB   64
#define NN   4096
#define CC   64
#define OUTF 64
#define K2   4
#define TM   128                       // sites per tile (GEMM M)
#define NTILES 2048                    // BB * NN / TM
#define GRID 296                       // 2 CTAs per SM
#define NTHREADS 128                   // 4 warps; warp owns 32 sites x 64 outs

#define BSTRB 528                      // B row stride bytes (conflict-free ldmatrix)
#define CHSTR 144                      // A chunk row stride bytes (64 kc * 2B + 16 pad)
#define WCH   (32 * CHSTR)             // 4608 B: one warp-chunk (32 sites x 64 kc)

// smem layout (bytes)
#define SM_BIAS 0                      // 64 floats
#define SM_MBAR 256                    // 4 warps * 4 bufs * 8B = 128B
#define SM_B    512                    // 64 rows * 528B = 33792
#define SM_A0   (SM_B + OUTF * BSTRB)  // 34304; then [warp][buf] chunk ring
#define SM_TOTAL (SM_A0 + 4 * 4 * WCH) // 108032 bytes -> 2 CTAs/SM

// Pre-converted x (fp16), set by prepass kernel
__device__ __align__(128) __half g_xh[BB * NN * CC];

__device__ __forceinline__ uint32_t smem_u32(const void* p) {
    uint32_t a;
    asm("{ .reg .u64 t; cvta.to.shared.u64 t, %1; cvt.u32.u64 %0, t; }" : "=r"(a) : "l"(p));
    return a;
}
__device__ __forceinline__ void ldsm_x4(uint32_t& r0, uint32_t& r1, uint32_t& r2, uint32_t& r3,
                                        uint32_t addr) {
    asm volatile("ldmatrix.sync.aligned.m8n8.x4.shared.b16 {%0,%1,%2,%3}, [%4];"
                 : "=r"(r0), "=r"(r1), "=r"(r2), "=r"(r3) : "r"(addr));
}
__device__ __forceinline__ void mma_fp16(float* acc, const uint32_t* a, const uint32_t* b) {
    asm volatile(
        "mma.sync.aligned.m16n8k16.row.col.f32.f16.f16.f32 "
        "{%0,%1,%2,%3}, {%4,%5,%6,%7}, {%8,%9}, {%0,%1,%2,%3};"
        : "+f"(acc[0]), "+f"(acc[1]), "+f"(acc[2]), "+f"(acc[3])
        : "r"(a[0]), "r"(a[1]), "r"(a[2]), "r"(a[3]), "r"(b[0]), "r"(b[1]));
}
__device__ __forceinline__ uint32_t pack_h2(float a, float b) {
    __half2 t = __floats2half2_rn(a, b);
    uint32_t u;
    memcpy(&u, &t, 4);
    return u;
}
__device__ __forceinline__ void mbar_wait(uint32_t mbar, uint32_t parity) {
    asm volatile(
        "{\n\t.reg .pred P1;\n\t"
        "WAIT_LOOP_%=:\n\t"
        "mbarrier.try_wait.parity.acquire.cta.shared::cta.b64 P1, [%0], %1, 0x989680;\n\t"
        "@P1 bra.uni WAIT_DONE_%=;\n\t"
        "bra.uni WAIT_LOOP_%=;\n\t"
        "WAIT_DONE_%=:\n\t}"
        :: "r"(mbar), "r"(parity) : "memory");
}

// ---- Prepass: convert fp32 x to fp16 (memory-bound) ----
__global__ __launch_bounds__(1024, 2)
void tohalf_kernel(const float* __restrict__ x)
{
    const int i = blockIdx.x * 1024 + threadIdx.x;     // float4 index, exact cover
    const float4 v = reinterpret_cast<const float4*>(x)[i];
    uint2 hv;
    hv.x = pack_h2(v.x, v.y);
    hv.y = pack_h2(v.z, v.w);
    reinterpret_cast<uint2*>(g_xh)[i] = hv;
}

__global__ __launch_bounds__(NTHREADS, 2)
void conv_fp16_m32_kernel(const float* __restrict__ W,
                          const float* __restrict__ bias,
                          const int*   __restrict__ kernel2,
                          float*       __restrict__ out)
{
    extern __shared__ char smem[];
    const uint32_t sbase = smem_u32(smem);
    const int tid  = threadIdx.x;
    const int wid  = tid >> 5;         // warp owns sites [wid*32, wid*32+32)
    const int lane = tid & 31;

    float* bias_s = reinterpret_cast<float*>(smem + SM_BIAS);
    if (tid < OUTF) bias_s[tid] = bias[tid];

    // ---- mbarrier init: one per (warp, buf) ----
    if (tid == 0) {
        #pragma unroll
        for (int i = 0; i < 16; ++i)
            asm volatile("mbarrier.init.shared.b64 [%0], %1;"
                         :: "r"(sbase + SM_MBAR + i * 8), "r"(1u) : "memory");
    }

    // ---- One-time: W -> fp16 B smem, layout [o][kc], 528B stride ----
    for (int idx = tid; idx < OUTF * 128; idx += NTHREADS) {   // 8192 kc-pairs
        const int o   = idx >> 7;
        const int kc0 = (idx & 127) << 1;
        const int k   = kc0 >> 6;
        const int c0  = kc0 & 63;
        const float* wp = W + k * (CC * OUTF) + c0 * OUTF + o;
        *reinterpret_cast<uint32_t*>(smem + SM_B + o * BSTRB + kc0 * 2) =
            pack_h2(wp[0], wp[OUTF]);
    }
    __syncthreads();                   // mbars + B + bias ready

    // ---- Tile-invariant ldmatrix per-lane addresses ----
    const int m  = lane >> 3;
    const int l7 = lane & 7;
    // A: two m16 blocks of the warp's 32 sites (144B-stride chunk)
    const uint32_t aoff0 = (uint32_t)((((m & 1) << 3) + l7) * CHSTR + ((m >> 1) << 4));
    const uint32_t aoff1 = aoff0 + 16 * CHSTR;
    // B: 4 n16 groups covering all 64 cols
    uint32_t bg[4];
    #pragma unroll
    for (int g = 0; g < 4; ++g)
        bg[g] = sbase + SM_B +
                (uint32_t)((g * 16 + ((m >> 1) << 3) + l7) * BSTRB + ((m & 1) << 4));

    const uint32_t warpA   = sbase + SM_A0 + (uint32_t)(wid * 4 * WCH);
    const uint32_t mb_base = sbase + SM_MBAR + (uint32_t)(wid * 4 * 8);

    // issue one warp-chunk gather: expect_tx + 32 x 128B bulk copies (all lanes)
    auto issue_chunk = [&](int buf, int b, int gi_lane) {
        const uint32_t mbar = mb_base + (uint32_t)(buf * 8);
        if (lane == 0)
            asm volatile("mbarrier.arrive.expect_tx.shared.b64 _, [%0], %1;"
                         :: "r"(mbar), "r"(4096u) : "memory");
        const uint32_t dst = warpA + (uint32_t)buf * WCH + (uint32_t)(lane * CHSTR);
        const __half* src = g_xh + ((size_t)b * NN + gi_lane) * CC;   // 128B row
        asm volatile(
            "cp.async.bulk.shared::cta.global.mbarrier::complete_tx::bytes "
            "[%0], [%1], 128, [%2];"
            :: "r"(dst), "l"(src), "r"(mbar) : "memory");
    };

    float acc[2][8][4];
    #pragma unroll
    for (int i = 0; i < 2; ++i)
        #pragma unroll
        for (int j = 0; j < 8; ++j)
            #pragma unroll
            for (int q = 0; q < 4; ++q)
                acc[i][j][q] = 0.0f;

    // MMA one chunk: buf j, B byte offset koff = j*128 (64 kc)
    auto mma_chunk = [&](int buf, uint32_t koff) {
        const uint32_t a0 = warpA + (uint32_t)buf * WCH + aoff0;
        const uint32_t a1 = warpA + (uint32_t)buf * WCH + aoff1;
        #pragma unroll
        for (int ks = 0; ks < 4; ++ks) {
            const uint32_t ka = (uint32_t)ks * 32;
            uint32_t A[2][4], B[4][4];
            ldsm_x4(A[0][0], A[0][1], A[0][2], A[0][3], a0 + ka);
            ldsm_x4(A[1][0], A[1][1], A[1][2], A[1][3], a1 + ka);
            #pragma unroll
            for (int g = 0; g < 4; ++g)
                ldsm_x4(B[g][0], B[g][1], B[g][2], B[g][3], bg[g] + koff + ka);
            #pragma unroll
            for (int mi = 0; mi < 2; ++mi)
                #pragma unroll
                for (int g = 0; g < 4; ++g) {
                    mma_fp16(acc[mi][2 * g],     A[mi], B[g] + 0);
                    mma_fp16(acc[mi][2 * g + 1], A[mi], B[g] + 2);
                }
        }
    };

    // ---- Prologue: tile t0, issue taps 0,1,2 (warp-local) ----
    int t_cur  = blockIdx.x;
    int b_cur  = t_cur >> 5;
    int n0_cur = (t_cur & 31) * TM;
    int4 idxA = reinterpret_cast<const int4*>(kernel2)[n0_cur + wid * 32 + lane];
    issue_chunk(0, b_cur, idxA.x);
    issue_chunk(1, b_cur, idxA.y);
    issue_chunk(2, b_cur, idxA.z);

    uint32_t par = 0;                  // parity bit per buffer

    // ---- Barrier-free warp-private tile loop ----
    while (t_cur < NTILES) {
        const int t_nxt = t_cur + GRID;
        const bool havenext = (t_nxt < NTILES);
        const int b_nxt  = t_nxt >> 5;
        const int n0_nxt = (t_nxt & 31) * TM;

        // prefetch next tile's indices (covered by MMA below)
        int4 idxB = idxA;
        if (havenext)
            idxB = reinterpret_cast<const int4*>(kernel2)[n0_nxt + wid * 32 + lane];

        // j=0: consume tap0; issue (t_cur, tap3) -> buf3
        mbar_wait(mb_base + 0, par & 1);  __syncwarp();
        issue_chunk(3, b_cur, idxA.w);
        mma_chunk(0, 0);

        // j=1: consume tap1; refill buf0 with (t_nxt, tap0)
        mbar_wait(mb_base + 8, (par >> 1) & 1);  __syncwarp();
        if (havenext) issue_chunk(0, b_nxt, idxB.x);
        mma_chunk(1, 128);

        // j=2: consume tap2; refill buf1
        mbar_wait(mb_base + 16, (par >> 2) & 1);  __syncwarp();
        if (havenext) issue_chunk(1, b_nxt, idxB.y);
        mma_chunk(2, 256);

        // j=3: consume tap3; refill buf2
        mbar_wait(mb_base + 24, (par >> 3) & 1);  __syncwarp();
        if (havenext) issue_chunk(2, b_nxt, idxB.z);
        mma_chunk(3, 384);

        par ^= 0xF;                    // all four buffers flipped phase this tile

        // ---- Epilogue: bias + store warp's 32 rows x 64 cols; reset acc ----
        {
            #pragma unroll
            for (int mi = 0; mi < 2; ++mi) {
                const size_t orow = (size_t)b_cur * NN + n0_cur + wid * 32 + mi * 16 + (lane >> 2);
                #pragma unroll
                for (int nb = 0; nb < 8; ++nb) {
                    const int col = nb * 8 + (lane & 3) * 2;
                    const float b0 = bias_s[col];
                    const float b1 = bias_s[col + 1];
                    float2 v0, v1;
                    v0.x = acc[mi][nb][0] + b0;  v0.y = acc[mi][nb][1] + b1;
                    v1.x = acc[mi][nb][2] + b0;  v1.y = acc[mi][nb][3] + b1;
                    *reinterpret_cast<float2*>(out + orow * OUTF + col)       = v0;
                    *reinterpret_cast<float2*>(out + (orow + 8) * OUTF + col) = v1;
                    acc[mi][nb][0] = 0.0f; acc[mi][nb][1] = 0.0f;
                    acc[mi][nb][2] = 0.0f; acc[mi][nb][3] = 0.0f;
                }
            }
        }

        t_cur = t_nxt;  b_cur = b_nxt;  n0_cur = n0_nxt;
        idxA = idxB;
    }
}

extern "C" void kernel_launch(void* const* d_in, const int* in_sizes, int n_in,
                              void* d_out, int out_size)
{
    const float* x    = (const float*)d_in[0];   // [B, N, C]
    const float* W    = (const float*)d_in[1];   // [K2, C, OUT]
    const float* bias = (const float*)d_in[2];   // [OUT]
    const int*   k2   = (const int*)d_in[3];     // [N, K2]
    float*       out  = (float*)d_out;           // [B, N, OUT]

    // Pass 1: x -> fp16
    tohalf_kernel<<<4096, 1024>>>(x);

    // Pass 2: fp16 gathered GEMM, m=32 warp tiles, bulk gather, warp-private rings
    cudaFuncSetAttribute(conv_fp16_m32_kernel,
                         cudaFuncAttributeMaxDynamicSharedMemorySize, SM_TOTAL);
    conv_fp16_m32_kernel<<<GRID, NTHREADS, SM_TOTAL>>>(W, bias, k2, out);
}